// round 15
// baseline (speedup 1.0000x reference)
#include <cuda_runtime.h>
#include <cuda_bf16.h>
#include <cuda_fp16.h>
#include <math.h>
#include <stdint.h>

#define NN 131072
#define EE 262144
#define DD 128
#define RR 128
#define NB 148
#define GOUT 384

#define TWO_PI_C1 6.2831854820251465f
#define TWO_PI_C2 (-1.7484556e-7f)
#define INV_2PI   0.15915494309189535f

// ---- k_msgT smem: double-buffered fp16 X ----
#define MXW 212
#define MXROW (MXW * 4)
#define XBUF 54272                      // one buffer
#define SMEM_MSG (2 * XBUF)             // 108544 -> 2 CTAs/SM

// ---- GRU smem ----
#define GXW 72
#define GSTG 388
#define G_XH 0
#define G_STG 9216
#define SMEM_GRU (G_STG + 49664)        // 58880 -> 2 CTAs/SM

// -------- device scratch --------
__device__ float g_sums[(size_t)NN * DD];
__device__ float g_cnt[NN];
__device__ int   g_tmax[NN];
__device__ uint2 g_gih[(size_t)NN * 96];
__device__ uint4 g_wph[2 * 8 * 26 * 32];
__device__ uint4 g_wpk[2 * 8 * 26 * 32];
__device__ uint4 g_gwh[2 * 24 * 8 * 32];
__device__ uint4 g_gwl[2 * 24 * 8 * 32];
__device__ uint32_t g_memh[(size_t)NN * 64];
__device__ uint32_t g_rawh[(size_t)EE * 64];

// ================= helpers =================
__device__ __forceinline__ void mma_h(float* c,
                                      uint32_t a0, uint32_t a1, uint32_t a2, uint32_t a3,
                                      uint32_t b0, uint32_t b1) {
    asm volatile("mma.sync.aligned.m16n8k16.row.col.f32.f16.f16.f32 "
        "{%0,%1,%2,%3}, {%4,%5,%6,%7}, {%8,%9}, {%0,%1,%2,%3};"
        : "+f"(c[0]), "+f"(c[1]), "+f"(c[2]), "+f"(c[3])
        : "r"(a0), "r"(a1), "r"(a2), "r"(a3), "r"(b0), "r"(b1));
}
__device__ __forceinline__ uint32_t hpack(float x, float y) {
    __half2 h = __floats2half2_rn(x, y);
    return *reinterpret_cast<uint32_t*>(&h);
}
__device__ __forceinline__ void hsplit(float2 p, uint32_t& hi, uint32_t& lo) {
    __half2 h = __floats2half2_rn(p.x, p.y);
    float rx = p.x - __half2float(__low2half(h));
    float ry = p.y - __half2float(__high2half(h));
    __half2 l = __floats2half2_rn(rx, ry);
    hi = *reinterpret_cast<uint32_t*>(&h);
    lo = *reinterpret_cast<uint32_t*>(&l);
}
__device__ __forceinline__ float cos_exact(float arg) {
    float k = rintf(__fmul_rn(arg, INV_2PI));
    float r = fmaf(-k, TWO_PI_C1, arg);
    r = fmaf(-k, TWO_PI_C2, r);
    return cosf(r);
}
__device__ __forceinline__ int permslot(int p) {
    int kk = p >> 3, pi = p & 7;
    return kk * 8 + ((pi < 4) ? 2 * pi : 2 * (pi - 4) + 1);
}
__device__ __forceinline__ uint32_t smem_u32(const void* p) {
    uint32_t a;
    asm("{ .reg .u64 t; cvta.to.shared.u64 t, %1; cvt.u32.u64 %0, t; }" : "=r"(a) : "l"(p));
    return a;
}
__device__ __forceinline__ void cp16(uint32_t dst, const void* src) {
    asm volatile("cp.async.cg.shared.global [%0], [%1], 16;" :: "r"(dst), "l"(src) : "memory");
}
#define CP_COMMIT() asm volatile("cp.async.commit_group;" ::: "memory")
#define CP_WAIT0()  asm volatile("cp.async.wait_group 0;" ::: "memory")

// ============================================================
__global__ void k_init() {
    size_t i = (size_t)blockIdx.x * blockDim.x + threadIdx.x;
    size_t stride = (size_t)gridDim.x * blockDim.x;
    float4* s4 = (float4*)g_sums;
    for (size_t idx = i; idx < (size_t)NN * DD / 4; idx += stride)
        s4[idx] = make_float4(0.f, 0.f, 0.f, 0.f);
    for (size_t idx = i; idx < NN; idx += stride) { g_cnt[idx] = 0.f; g_tmax[idx] = 0; }
}

// ============================================================
__global__ void k_packmem(const float* __restrict__ mem) {
    size_t i = (size_t)blockIdx.x * blockDim.x + threadIdx.x;
    size_t stride = (size_t)gridDim.x * blockDim.x;
    for (size_t idx = i; idx < (size_t)NN * 64; idx += stride) {
        size_t n = idx >> 6; int p = (int)(idx & 63);
        float2 v = *(const float2*)(mem + n * 128 + 2 * p);
        g_memh[n * 64 + permslot(p)] = hpack(v.x, v.y);
    }
}
__global__ void k_packraw(const float* __restrict__ raw) {
    size_t i = (size_t)blockIdx.x * blockDim.x + threadIdx.x;
    size_t stride = (size_t)gridDim.x * blockDim.x;
    for (size_t idx = i; idx < (size_t)EE * 64; idx += stride) {
        size_t e = idx >> 6; int p = (int)(idx & 63);
        float2 v = *(const float2*)(raw + e * 128 + 2 * p);
        g_rawh[e * 64 + permslot(p)] = hpack(v.x, v.y);
    }
}

// ============================================================
__global__ void k_pack(const float* __restrict__ Ws, const float* __restrict__ Wd) {
    int lane = threadIdx.x;
    int b = blockIdx.x;
    int side = b / 208;
    int rem = b - side * 208;
    int rg = rem / 26, kg = rem - (rem / 26) * 26;
    const float* W = side ? Wd : Ws;
    int g = lane >> 2, tig = lane & 3;
    int r0 = rg * 16;
    int rows[2] = {r0 + g, r0 + g + 8};
    int cols[2] = {kg * 16 + 2 * tig, kg * 16 + 8 + 2 * tig};
    uint32_t wh[4], wl[4];
    #pragma unroll
    for (int cc = 0; cc < 2; cc++)
        #pragma unroll
        for (int rr = 0; rr < 2; rr++) {
            float2 v = *(const float2*)(W + (size_t)rows[rr] * 416 + cols[cc]);
            hsplit(v, wh[cc * 2 + rr], wl[cc * 2 + rr]);
        }
    g_wph[(size_t)b * 32 + lane] = make_uint4(wh[0], wh[1], wh[2], wh[3]);
    g_wpk[(size_t)b * 32 + lane] = make_uint4(wl[0], wl[1], wl[2], wl[3]);
}

__global__ void k_packgru(const float* __restrict__ Wih, const float* __restrict__ Whh) {
    int lane = threadIdx.x;
    int b = blockIdx.x;
    int m = b / 192;
    int rem = b - m * 192;
    int rtile = rem >> 3, kk = rem & 7;
    const float* W = m ? Whh : Wih;
    int g = lane >> 2, tig = lane & 3;
    int r0 = rtile * 16;
    int rows[2] = {r0 + g, r0 + g + 8};
    int cols[2] = {kk * 16 + 2 * tig, kk * 16 + 8 + 2 * tig};
    uint32_t wh[4], wl[4];
    #pragma unroll
    for (int cc = 0; cc < 2; cc++)
        #pragma unroll
        for (int rr = 0; rr < 2; rr++) {
            float2 v = *(const float2*)(W + (size_t)rows[rr] * 128 + cols[cc]);
            hsplit(v, wh[cc * 2 + rr], wl[cc * 2 + rr]);
        }
    g_gwh[(size_t)b * 32 + lane] = make_uint4(wh[0], wh[1], wh[2], wh[3]);
    g_gwl[(size_t)b * 32 + lane] = make_uint4(wl[0], wl[1], wl[2], wl[3]);
}

// ============================================================
// Message MLP: fp16 2-sweep, cp.async double-buffered gather.
// 512 threads / 16 warps, K-split warp pairs, 64-event tiles.
// ============================================================
__global__ void __launch_bounds__(512, 2) k_msgT(
    const float* __restrict__ tw,  const float* __restrict__ tb,
    const float* __restrict__ bs,  const float* __restrict__ bd,
    const int* __restrict__ src, const int* __restrict__ dst,
    const int* __restrict__ tt,  const int* __restrict__ lu)
{
    extern __shared__ char smem[];
    const uint32_t sb = smem_u32(smem);

    const int tid  = threadIdx.x;
    const int wid  = tid >> 5;
    const int lane = tid & 31;
    const int g    = lane >> 2;
    const int tig  = lane & 3;
    const int half = wid >> 3;
    const int ks   = half * 13;
    const int side = (blockIdx.x >= NB);
    const int bid  = side ? blockIdx.x - NB : blockIdx.x;
    const float* bias = side ? bd : bs;
    const int r0 = (wid & 7) * 16;
    const size_t wbase = ((size_t)side * 208 + (size_t)(wid & 7) * 26) * 32 + lane;

    const float b0r = bias[r0 + g], b1r = bias[r0 + g + 8];
    const float twj = tw[lane], tbj = tb[lane];
    const int STRIDE = NB * 64;

    // NOTE: no variable named `buf`/`p` may be declared inside this macro's
    // body before uses of (BO) — BO references the caller's buffer index.
#define GATHER(E0, BO) do {                                                   \
    uint32_t xdst = sb + (uint32_t)(BO);                                      \
    _Pragma("unroll")                                                         \
    for (int it = 0; it < 6; it++) {                                          \
        int idx = tid + it * 512;                                             \
        int ev = idx / 48, c16 = idx - (idx / 48) * 48;                       \
        int e = (E0) + ev;                                                    \
        int vs = src[e], vd = dst[e];                                         \
        int a = side ? vd : vs, b = side ? vs : vd;                           \
        size_t base; const uint32_t* ph;                                      \
        if (c16 < 16)      { base = (size_t)a * 64 + c16 * 4;        ph = g_memh; } \
        else if (c16 < 32) { base = (size_t)b * 64 + (c16 - 16) * 4; ph = g_memh; } \
        else               { base = (size_t)e * 64 + (c16 - 32) * 4; ph = g_rawh; } \
        cp16(xdst + (uint32_t)(ev * MXROW + c16 * 16), ph + base);            \
    }                                                                         \
    CP_COMMIT();                                                              \
    _Pragma("unroll")                                                         \
    for (int z = 0; z < 4; z++) {                                             \
        int ev = wid + z * 16;                                                \
        int e = (E0) + ev;                                                    \
        int a = side ? dst[e] : src[e];                                       \
        float trel = __fsub_rn((float)tt[e], (float)lu[a]);                   \
        float arg  = __fadd_rn(__fmul_rn(trel, twj), tbj);                    \
        float c = cos_exact(arg);                                             \
        int kwd  = 384 + lane;                                                \
        int pw   = kwd >> 1;                                                  \
        int pi = pw & 7, kq = pw >> 3;                                        \
        int w = kq * 8 + ((pi < 4) ? 2 * pi : 2 * (pi - 4) + 1);              \
        *(__half*)((char*)smem + (uint32_t)(BO) + ev * MXROW + w * 4 + (kwd & 1) * 2) = \
            __float2half_rn(c);                                               \
    }                                                                         \
} while (0)

    GATHER(bid * 64, 0);
    int buf = 0;

    for (int e0 = bid * 64; e0 < EE; e0 += STRIDE) {
        CP_WAIT0();
        __syncthreads();            // tile e0 fully visible in buffer `buf`
        int e1 = e0 + STRIDE;
        if (e1 < EE) GATHER(e1, (buf ^ 1) * XBUF);

        uint32_t* xh = (uint32_t*)(smem + buf * XBUF);
        float* stage = (float*)(smem + buf * XBUF);

        // ---- mma: 2 sweeps over this warp's 13 k-steps ----
        float acc[8][4];
        #pragma unroll
        for (int et = 0; et < 8; et++)
            acc[et][0] = acc[et][1] = acc[et][2] = acc[et][3] = 0.f;
        #pragma unroll 1
        for (int kk = 0; kk < 13; kk++) {
            int kg = ks + kk;
            uint4 wh = __ldg(&g_wph[wbase + (size_t)kg * 32]);
            uint4 wl = __ldg(&g_wpk[wbase + (size_t)kg * 32]);
            #pragma unroll
            for (int et = 0; et < 8; et++) {
                uint2 b = *(const uint2*)(xh + (et * 8 + g) * MXW + kg * 8 + 2 * tig);
                mma_h(acc[et], wh.x, wh.y, wh.z, wh.w, b.x, b.y);
                mma_h(acc[et], wl.x, wl.y, wl.z, wl.w, b.x, b.y);
            }
        }
        __syncthreads();            // xh reads done -> stage overlays

        // ---- combine K halves through stage ----
        if (half) {
            #pragma unroll
            for (int et = 0; et < 8; et++) {
                int evl = et * 8 + 2 * tig;
                stage[evl * 132 + r0 + g]           = acc[et][0];
                stage[(evl + 1) * 132 + r0 + g]     = acc[et][1];
                stage[evl * 132 + r0 + g + 8]       = acc[et][2];
                stage[(evl + 1) * 132 + r0 + g + 8] = acc[et][3];
            }
        }
        __syncthreads();
        if (!half) {
            #pragma unroll
            for (int et = 0; et < 8; et++) {
                int evl = et * 8 + 2 * tig;
                float* s0 = stage + evl * 132;
                float* s1 = stage + (evl + 1) * 132;
                s0[r0 + g]     = fmaxf(acc[et][0] + s0[r0 + g]     + b0r, 0.f);
                s1[r0 + g]     = fmaxf(acc[et][1] + s1[r0 + g]     + b0r, 0.f);
                s0[r0 + g + 8] = fmaxf(acc[et][2] + s0[r0 + g + 8] + b1r, 0.f);
                s1[r0 + g + 8] = fmaxf(acc[et][3] + s1[r0 + g + 8] + b1r, 0.f);
            }
        }
        __syncthreads();

        // ---- scatter float4 atomics ----
        #pragma unroll
        for (int it = 0; it < 4; it++) {
            int idx = tid + it * 512;
            int ev = idx >> 5, q = idx & 31;
            int e = e0 + ev;
            int key = side ? dst[e] : src[e];
            float4 v = *(const float4*)(stage + ev * 132 + q * 4);
            atomicAdd((float4*)&g_sums[(size_t)key * DD + q * 4], v);
        }
        if (tid < 64) {
            int e = e0 + tid;
            int key = side ? dst[e] : src[e];
            atomicAdd(&g_cnt[key], 1.0f);
            atomicMax(&g_tmax[key], tt[e]);
        }
        __syncthreads();            // stage free before next tile's overlay
        buf ^= 1;
    }
#undef GATHER
}

// ============================================================
// gi = aggr @ W_ih^T + b_ih (round-13 proven)
// ============================================================
__global__ void __launch_bounds__(384, 2) k_gi3(const float* __restrict__ bih)
{
    extern __shared__ char smem[];
    uint32_t* xh = (uint32_t*)(smem + G_XH);
    float* stage = (float*)(smem + G_STG);

    const int tid = threadIdx.x;
    const int wid = tid >> 5;
    const int lane = tid & 31;
    const int g = lane >> 2, tig = lane & 3;
    const int stride = gridDim.x * 32;

    float bv[2][2];
    #pragma unroll
    for (int rt = 0; rt < 2; rt++) {
        bv[rt][0] = bih[wid * 32 + rt * 16 + g];
        bv[rt][1] = bih[wid * 32 + rt * 16 + g + 8];
    }

    float4 pv[3]; float pc[3];
#define PREF_GI(N0) do {                                                   \
    _Pragma("unroll")                                                      \
    for (int it = 0; it < 3; it++) {                                       \
        int idx = tid + it * 384;                                          \
        if (idx < 1024) {                                                  \
            int n = (N0) + (idx >> 5);                                     \
            pv[it] = ((const float4*)g_sums)[(size_t)n * 32 + (idx & 31)]; \
            pc[it] = g_cnt[n];                                             \
        }                                                                  \
    }                                                                      \
} while (0)

    PREF_GI(blockIdx.x * 32);
    for (int n0 = blockIdx.x * 32; n0 < NN; n0 += stride) {
        #pragma unroll
        for (int it = 0; it < 3; it++) {
            int idx = tid + it * 384;
            if (idx < 1024) {
                int n = idx >> 5, c4 = idx & 31;
                float inv = 1.0f / fmaxf(pc[it], 1.0f);
                float4 v = pv[it];
                int q = c4 & 3;
                int w = (c4 >> 2) * 8 + (q >> 1) + (q & 1) * 4;
                xh[n * GXW + w]     = hpack(v.x * inv, v.y * inv);
                xh[n * GXW + w + 2] = hpack(v.z * inv, v.w * inv);
            }
        }
        __syncthreads();
        if (n0 + stride < NN) PREF_GI(n0 + stride);

        float acc[2][4][4];
        #pragma unroll
        for (int rt = 0; rt < 2; rt++)
            #pragma unroll
            for (int et = 0; et < 4; et++)
                acc[rt][et][0] = acc[rt][et][1] = acc[rt][et][2] = acc[rt][et][3] = 0.f;
        #pragma unroll 1
        for (int kk = 0; kk < 8; kk++) {
            uint2 b[4];
            #pragma unroll
            for (int et = 0; et < 4; et++)
                b[et] = *(const uint2*)(xh + (et * 8 + g) * GXW + kk * 8 + 2 * tig);
            #pragma unroll
            for (int rt = 0; rt < 2; rt++) {
                size_t fb = (((size_t)(wid * 2 + rt)) * 8 + kk) * 32 + lane;
                uint4 wh = __ldg(&g_gwh[fb]);
                uint4 wl = __ldg(&g_gwl[fb]);
                #pragma unroll
                for (int et = 0; et < 4; et++) {
                    mma_h(acc[rt][et], wh.x, wh.y, wh.z, wh.w, b[et].x, b[et].y);
                    mma_h(acc[rt][et], wl.x, wl.y, wl.z, wl.w, b[et].x, b[et].y);
                }
            }
        }
        #pragma unroll
        for (int rt = 0; rt < 2; rt++) {
            int r = wid * 32 + rt * 16 + g;
            #pragma unroll
            for (int et = 0; et < 4; et++) {
                int nl = et * 8 + 2 * tig;
                stage[nl * GSTG + r]           = acc[rt][et][0] + bv[rt][0];
                stage[(nl + 1) * GSTG + r]     = acc[rt][et][1] + bv[rt][0];
                stage[nl * GSTG + r + 8]       = acc[rt][et][2] + bv[rt][1];
                stage[(nl + 1) * GSTG + r + 8] = acc[rt][et][3] + bv[rt][1];
            }
        }
        __syncthreads();

        #pragma unroll
        for (int it = 0; it < 8; it++) {
            int idx = tid + it * 384;
            int n = idx / 96, c4 = idx - (idx / 96) * 96;
            float4 v = *(const float4*)(stage + n * GSTG + c4 * 4);
            uint2 u;
            u.x = hpack(v.x, v.y);
            u.y = hpack(v.z, v.w);
            g_gih[(size_t)(n0 + n) * 96 + c4] = u;
        }
    }
#undef PREF_GI
}

// ============================================================
// gh + fused GRU combine (round-13 proven)
// ============================================================
__global__ void __launch_bounds__(384, 2) k_out3(
    const float* __restrict__ bhh, const float* __restrict__ mem,
    float* __restrict__ out)
{
    extern __shared__ char smem[];
    uint32_t* xh = (uint32_t*)(smem + G_XH);
    float* stage = (float*)(smem + G_STG);

    const int tid = threadIdx.x;
    const int wid = tid >> 5;
    const int lane = tid & 31;
    const int g = lane >> 2, tig = lane & 3;
    const int stride = gridDim.x * 32;

    float bv[2][2];
    #pragma unroll
    for (int rt = 0; rt < 2; rt++) {
        bv[rt][0] = bhh[wid * 32 + rt * 16 + g];
        bv[rt][1] = bhh[wid * 32 + rt * 16 + g + 8];
    }

    uint4 pu[2];
#define PREF_OUT(N0) do {                                                  \
    _Pragma("unroll")                                                      \
    for (int it = 0; it < 2; it++) {                                       \
        int idx = tid + it * 384;                                          \
        if (idx < 512) {                                                   \
            int n = (N0) + (idx >> 4), c16 = idx & 15;                     \
            pu[it] = *(const uint4*)(g_memh + (size_t)n * 64 + c16 * 4);   \
        }                                                                  \
    }                                                                      \
} while (0)

    PREF_OUT(blockIdx.x * 32);
    for (int n0 = blockIdx.x * 32; n0 < NN; n0 += stride) {
        #pragma unroll
        for (int it = 0; it < 2; it++) {
            int idx = tid + it * 384;
            if (idx < 512) {
                int n = idx >> 4, c16 = idx & 15;
                *(uint4*)(xh + n * GXW + c16 * 4) = pu[it];
            }
        }
        __syncthreads();
        if (n0 + stride < NN) PREF_OUT(n0 + stride);

        float acc[2][4][4];
        #pragma unroll
        for (int rt = 0; rt < 2; rt++)
            #pragma unroll
            for (int et = 0; et < 4; et++)
                acc[rt][et][0] = acc[rt][et][1] = acc[rt][et][2] = acc[rt][et][3] = 0.f;
        #pragma unroll 1
        for (int kk = 0; kk < 8; kk++) {
            uint2 b[4];
            #pragma unroll
            for (int et = 0; et < 4; et++)
                b[et] = *(const uint2*)(xh + (et * 8 + g) * GXW + kk * 8 + 2 * tig);
            #pragma unroll
            for (int rt = 0; rt < 2; rt++) {
                size_t fb = (((size_t)24 + (wid * 2 + rt)) * 8 + kk) * 32 + lane;
                uint4 wh = __ldg(&g_gwh[fb]);
                uint4 wl = __ldg(&g_gwl[fb]);
                #pragma unroll
                for (int et = 0; et < 4; et++) {
                    mma_h(acc[rt][et], wh.x, wh.y, wh.z, wh.w, b[et].x, b[et].y);
                    mma_h(acc[rt][et], wl.x, wl.y, wl.z, wl.w, b[et].x, b[et].y);
                }
            }
        }
        #pragma unroll
        for (int rt = 0; rt < 2; rt++) {
            int r = wid * 32 + rt * 16 + g;
            #pragma unroll
            for (int et = 0; et < 4; et++) {
                int nl = et * 8 + 2 * tig;
                stage[nl * GSTG + r]           = acc[rt][et][0] + bv[rt][0];
                stage[(nl + 1) * GSTG + r]     = acc[rt][et][1] + bv[rt][0];
                stage[nl * GSTG + r + 8]       = acc[rt][et][2] + bv[rt][1];
                stage[(nl + 1) * GSTG + r + 8] = acc[rt][et][3] + bv[rt][1];
            }
        }
        __syncthreads();

        #pragma unroll
        for (int it = 0; it < 3; it++) {
            int idx = tid + it * 384;
            if (idx < 1024) {
                int n = idx >> 5, c4 = idx & 31;
                size_t gb = (size_t)(n0 + n) * 96 + c4;
                uint2 uir = g_gih[gb];
                uint2 uiz = g_gih[gb + 32];
                uint2 uin = g_gih[gb + 64];
                float2 ir01 = __half22float2(*reinterpret_cast<__half2*>(&uir.x));
                float2 ir23 = __half22float2(*reinterpret_cast<__half2*>(&uir.y));
                float2 iz01 = __half22float2(*reinterpret_cast<__half2*>(&uiz.x));
                float2 iz23 = __half22float2(*reinterpret_cast<__half2*>(&uiz.y));
                float2 in01 = __half22float2(*reinterpret_cast<__half2*>(&uin.x));
                float2 in23 = __half22float2(*reinterpret_cast<__half2*>(&uin.y));
                float4 hr = *(const float4*)(stage + n * GSTG + c4 * 4);
                float4 hz = *(const float4*)(stage + n * GSTG + 128 + c4 * 4);
                float4 hn = *(const float4*)(stage + n * GSTG + 256 + c4 * 4);
                float4 m = ((const float4*)mem)[(size_t)(n0 + n) * 32 + c4];
                float4 o;
                { float rg = 1.f/(1.f+expf(-(ir01.x+hr.x))), zg = 1.f/(1.f+expf(-(iz01.x+hz.x)));
                  o.x = (1.f-zg)*tanhf(in01.x+rg*hn.x) + zg*m.x; }
                { float rg = 1.f/(1.f+expf(-(ir01.y+hr.y))), zg = 1.f/(1.f+expf(-(iz01.y+hz.y)));
                  o.y = (1.f-zg)*tanhf(in01.y+rg*hn.y) + zg*m.y; }
                { float rg = 1.f/(1.f+expf(-(ir23.x+hr.z))), zg = 1.f/(1.f+expf(-(iz23.x+hz.z)));
                  o.z = (1.f-zg)*tanhf(in23.x+rg*hn.z) + zg*m.z; }
                { float rg = 1.f/(1.f+expf(-(ir23.y+hr.w))), zg = 1.f/(1.f+expf(-(iz23.y+hz.w)));
                  o.w = (1.f-zg)*tanhf(in23.y+rg*hn.w) + zg*m.w; }
                ((float4*)out)[(size_t)(n0 + n) * 32 + c4] = o;
            }
        }
    }
#undef PREF_OUT
}

// ============================================================
__global__ void k_lu(float* __restrict__ out) {
    int i = blockIdx.x * blockDim.x + threadIdx.x;
    if (i < NN)
        out[(size_t)NN * DD + i] = (g_cnt[i] > 0.f) ? (float)g_tmax[i] : 0.f;
}

// ============================================================
extern "C" void kernel_launch(void* const* d_in, const int* in_sizes, int n_in,
                              void* d_out, int out_size)
{
    const float* mem = (const float*)d_in[0];
    const float* raw = (const float*)d_in[1];
    const float* tw  = (const float*)d_in[2];
    const float* tb  = (const float*)d_in[3];
    const float* Ws  = (const float*)d_in[4];
    const float* bs  = (const float*)d_in[5];
    const float* Wd  = (const float*)d_in[6];
    const float* bd  = (const float*)d_in[7];
    const float* Wih = (const float*)d_in[8];
    const float* Whh = (const float*)d_in[9];
    const float* bih = (const float*)d_in[10];
    const float* bhh = (const float*)d_in[11];
    const int* src = (const int*)d_in[12];
    const int* dst = (const int*)d_in[13];
    const int* tt  = (const int*)d_in[14];
    const int* lu  = (const int*)d_in[15];
    float* out = (float*)d_out;

    cudaFuncSetAttribute(k_msgT, cudaFuncAttributeMaxDynamicSharedMemorySize, SMEM_MSG);
    cudaFuncSetAttribute(k_gi3,  cudaFuncAttributeMaxDynamicSharedMemorySize, SMEM_GRU);
    cudaFuncSetAttribute(k_out3, cudaFuncAttributeMaxDynamicSharedMemorySize, SMEM_GRU);

    k_init<<<2048, 256>>>();
    k_pack<<<416, 32>>>(Ws, Wd);
    k_packgru<<<384, 32>>>(Wih, Whh);
    k_packmem<<<2048, 256>>>(mem);
    k_packraw<<<2048, 256>>>(raw);
    k_msgT<<<2 * NB, 512, SMEM_MSG>>>(tw, tb, bs, bd, src, dst, tt, lu);
    k_gi3 <<<NB, 384, SMEM_GRU>>>(bih);
    k_out3<<<NB, 384, SMEM_GRU>>>(bhh, mem, out);
    if (out_size >= NN * DD + NN)
        k_lu<<<(NN + 255) / 256, 256>>>(out);
}

// round 16
// speedup vs baseline: 1.2154x; 1.2154x over previous
#include <cuda_runtime.h>
#include <cuda_fp16.h>
#include <math.h>
#include <stdint.h>

#define NN 131072
#define EE 262144
#define DD 128
#define RR 128
#define NB 148
#define GOUT 384

#define TWO_PI_C1 6.2831854820251465f
#define TWO_PI_C2 (-1.7484556e-7f)
#define INV_2PI   0.15915494309189535f

// ---- k_msgT smem: double-buffered fp16 X ----
#define MXW 212
#define MXROW (MXW * 4)
#define XBUF 54272
#define SMEM_MSG (2 * XBUF)             // 108544 -> 2 CTAs/SM

// ---- fused GRU smem ----
#define GXW 72
#define GSTG 388
#define G2_XGI 0                        // 32*72*4 = 9216
#define G2_XGH 9216                     // 9216
#define G2_SGI 18432                    // 32*388*4 = 49664
#define G2_SGH (18432 + 49664)          // 68096
#define SMEM_GRU2 (68096 + 49664)       // 117760 -> 1 CTA/SM

// -------- device scratch --------
__device__ float g_sums[(size_t)NN * DD];
__device__ float g_cnt[NN];
__device__ int   g_tmax[NN];
__device__ uint4 g_wph[2 * 8 * 26 * 32];          // msg W fp16 fragments
__device__ uint4 g_gwh[2 * 24 * 8 * 32];          // GRU W fp16 fragments
__device__ uint32_t g_memh[(size_t)NN * 64];      // memory fp16, permuted
__device__ uint32_t g_rawh[(size_t)EE * 64];      // raw fp16, permuted

// ================= helpers =================
__device__ __forceinline__ void mma_h(float* c,
                                      uint32_t a0, uint32_t a1, uint32_t a2, uint32_t a3,
                                      uint32_t b0, uint32_t b1) {
    asm volatile("mma.sync.aligned.m16n8k16.row.col.f32.f16.f16.f32 "
        "{%0,%1,%2,%3}, {%4,%5,%6,%7}, {%8,%9}, {%0,%1,%2,%3};"
        : "+f"(c[0]), "+f"(c[1]), "+f"(c[2]), "+f"(c[3])
        : "r"(a0), "r"(a1), "r"(a2), "r"(a3), "r"(b0), "r"(b1));
}
__device__ __forceinline__ uint32_t hpack(float x, float y) {
    __half2 h = __floats2half2_rn(x, y);
    return *reinterpret_cast<uint32_t*>(&h);
}
__device__ __forceinline__ float cos_exact(float arg) {
    float k = rintf(__fmul_rn(arg, INV_2PI));
    float r = fmaf(-k, TWO_PI_C1, arg);
    r = fmaf(-k, TWO_PI_C2, r);
    return cosf(r);
}
__device__ __forceinline__ int permslot(int p) {
    int kk = p >> 3, pi = p & 7;
    return kk * 8 + ((pi < 4) ? 2 * pi : 2 * (pi - 4) + 1);
}
__device__ __forceinline__ uint32_t smem_u32(const void* p) {
    uint32_t a;
    asm("{ .reg .u64 t; cvta.to.shared.u64 t, %1; cvt.u32.u64 %0, t; }" : "=r"(a) : "l"(p));
    return a;
}
__device__ __forceinline__ void cp16(uint32_t dst, const void* src) {
    asm volatile("cp.async.cg.shared.global [%0], [%1], 16;" :: "r"(dst), "l"(src) : "memory");
}
#define CP_COMMIT() asm volatile("cp.async.commit_group;" ::: "memory")
#define CP_WAIT0()  asm volatile("cp.async.wait_group 0;" ::: "memory")

// ============================================================
__global__ void k_init() {
    size_t i = (size_t)blockIdx.x * blockDim.x + threadIdx.x;
    size_t stride = (size_t)gridDim.x * blockDim.x;
    float4* s4 = (float4*)g_sums;
    for (size_t idx = i; idx < (size_t)NN * DD / 4; idx += stride)
        s4[idx] = make_float4(0.f, 0.f, 0.f, 0.f);
    for (size_t idx = i; idx < NN; idx += stride) { g_cnt[idx] = 0.f; g_tmax[idx] = 0; }
}

// ============================================================
__global__ void k_packmem(const float* __restrict__ mem) {
    size_t i = (size_t)blockIdx.x * blockDim.x + threadIdx.x;
    size_t stride = (size_t)gridDim.x * blockDim.x;
    for (size_t idx = i; idx < (size_t)NN * 64; idx += stride) {
        size_t n = idx >> 6; int p = (int)(idx & 63);
        float2 v = *(const float2*)(mem + n * 128 + 2 * p);
        g_memh[n * 64 + permslot(p)] = hpack(v.x, v.y);
    }
}
__global__ void k_packraw(const float* __restrict__ raw) {
    size_t i = (size_t)blockIdx.x * blockDim.x + threadIdx.x;
    size_t stride = (size_t)gridDim.x * blockDim.x;
    for (size_t idx = i; idx < (size_t)EE * 64; idx += stride) {
        size_t e = idx >> 6; int p = (int)(idx & 63);
        float2 v = *(const float2*)(raw + e * 128 + 2 * p);
        g_rawh[e * 64 + permslot(p)] = hpack(v.x, v.y);
    }
}

// ============================================================
__global__ void k_pack(const float* __restrict__ Ws, const float* __restrict__ Wd) {
    int lane = threadIdx.x;
    int b = blockIdx.x;
    int side = b / 208;
    int rem = b - side * 208;
    int rg = rem / 26, kg = rem - (rem / 26) * 26;
    const float* W = side ? Wd : Ws;
    int g = lane >> 2, tig = lane & 3;
    int r0 = rg * 16;
    int rows[2] = {r0 + g, r0 + g + 8};
    int cols[2] = {kg * 16 + 2 * tig, kg * 16 + 8 + 2 * tig};
    uint32_t wh[4];
    #pragma unroll
    for (int cc = 0; cc < 2; cc++)
        #pragma unroll
        for (int rr = 0; rr < 2; rr++) {
            float2 v = *(const float2*)(W + (size_t)rows[rr] * 416 + cols[cc]);
            wh[cc * 2 + rr] = hpack(v.x, v.y);
        }
    g_wph[(size_t)b * 32 + lane] = make_uint4(wh[0], wh[1], wh[2], wh[3]);
}

__global__ void k_packgru(const float* __restrict__ Wih, const float* __restrict__ Whh) {
    int lane = threadIdx.x;
    int b = blockIdx.x;
    int m = b / 192;
    int rem = b - m * 192;
    int rtile = rem >> 3, kk = rem & 7;
    const float* W = m ? Whh : Wih;
    int g = lane >> 2, tig = lane & 3;
    int r0 = rtile * 16;
    int rows[2] = {r0 + g, r0 + g + 8};
    int cols[2] = {kk * 16 + 2 * tig, kk * 16 + 8 + 2 * tig};
    uint32_t wh[4];
    #pragma unroll
    for (int cc = 0; cc < 2; cc++)
        #pragma unroll
        for (int rr = 0; rr < 2; rr++) {
            float2 v = *(const float2*)(W + (size_t)rows[rr] * 128 + cols[cc]);
            wh[cc * 2 + rr] = hpack(v.x, v.y);
        }
    g_gwh[(size_t)b * 32 + lane] = make_uint4(wh[0], wh[1], wh[2], wh[3]);
}

// ============================================================
// Message MLP: fp16 single-sweep, cp.async double-buffered gather.
// 512 threads / 16 warps, K-split warp pairs, 64-event tiles.
// ============================================================
__global__ void __launch_bounds__(512, 2) k_msgT(
    const float* __restrict__ tw,  const float* __restrict__ tb,
    const float* __restrict__ bs,  const float* __restrict__ bd,
    const int* __restrict__ src, const int* __restrict__ dst,
    const int* __restrict__ tt,  const int* __restrict__ lu)
{
    extern __shared__ char smem[];
    const uint32_t sb = smem_u32(smem);

    const int tid  = threadIdx.x;
    const int wid  = tid >> 5;
    const int lane = tid & 31;
    const int g    = lane >> 2;
    const int tig  = lane & 3;
    const int half = wid >> 3;
    const int ks   = half * 13;
    const int side = (blockIdx.x >= NB);
    const int bid  = side ? blockIdx.x - NB : blockIdx.x;
    const float* bias = side ? bd : bs;
    const int r0 = (wid & 7) * 16;
    const size_t wbase = ((size_t)side * 208 + (size_t)(wid & 7) * 26) * 32 + lane;

    const float b0r = bias[r0 + g], b1r = bias[r0 + g + 8];
    const float twj = tw[lane], tbj = tb[lane];
    const int STRIDE = NB * 64;

    // hygiene: no inner variable may shadow the caller's buffer index.
#define GATHER(E0, BO) do {                                                   \
    uint32_t xdst = sb + (uint32_t)(BO);                                      \
    _Pragma("unroll")                                                         \
    for (int it = 0; it < 6; it++) {                                          \
        int idx = tid + it * 512;                                             \
        int ev = idx / 48, c16 = idx - (idx / 48) * 48;                       \
        int e = (E0) + ev;                                                    \
        int vs = src[e], vd = dst[e];                                         \
        int a = side ? vd : vs, b = side ? vs : vd;                           \
        size_t base; const uint32_t* ph;                                      \
        if (c16 < 16)      { base = (size_t)a * 64 + c16 * 4;        ph = g_memh; } \
        else if (c16 < 32) { base = (size_t)b * 64 + (c16 - 16) * 4; ph = g_memh; } \
        else               { base = (size_t)e * 64 + (c16 - 32) * 4; ph = g_rawh; } \
        cp16(xdst + (uint32_t)(ev * MXROW + c16 * 16), ph + base);            \
    }                                                                         \
    CP_COMMIT();                                                              \
    _Pragma("unroll")                                                         \
    for (int z = 0; z < 4; z++) {                                             \
        int ev = wid + z * 16;                                                \
        int e = (E0) + ev;                                                    \
        int a = side ? dst[e] : src[e];                                       \
        float trel = __fsub_rn((float)tt[e], (float)lu[a]);                   \
        float arg  = __fadd_rn(__fmul_rn(trel, twj), tbj);                    \
        float c = cos_exact(arg);                                             \
        int kwd  = 384 + lane;                                                \
        int pw   = kwd >> 1;                                                  \
        int pi = pw & 7, kq = pw >> 3;                                        \
        int w = kq * 8 + ((pi < 4) ? 2 * pi : 2 * (pi - 4) + 1);              \
        *(__half*)((char*)smem + (uint32_t)(BO) + ev * MXROW + w * 4 + (kwd & 1) * 2) = \
            __float2half_rn(c);                                               \
    }                                                                         \
} while (0)

    GATHER(bid * 64, 0);
    int buf = 0;

    for (int e0 = bid * 64; e0 < EE; e0 += STRIDE) {
        CP_WAIT0();
        __syncthreads();
        int e1 = e0 + STRIDE;
        if (e1 < EE) GATHER(e1, (buf ^ 1) * XBUF);

        uint32_t* xh = (uint32_t*)(smem + buf * XBUF);
        float* stage = (float*)(smem + buf * XBUF);

        // ---- mma: single fp16 sweep over this warp's 13 k-steps ----
        float acc[8][4];
        #pragma unroll
        for (int et = 0; et < 8; et++)
            acc[et][0] = acc[et][1] = acc[et][2] = acc[et][3] = 0.f;
        #pragma unroll 1
        for (int kk = 0; kk < 13; kk++) {
            int kg = ks + kk;
            uint4 wh = __ldg(&g_wph[wbase + (size_t)kg * 32]);
            #pragma unroll
            for (int et = 0; et < 8; et++) {
                uint2 b = *(const uint2*)(xh + (et * 8 + g) * MXW + kg * 8 + 2 * tig);
                mma_h(acc[et], wh.x, wh.y, wh.z, wh.w, b.x, b.y);
            }
        }
        __syncthreads();            // xh reads done -> stage overlays

        if (half) {
            #pragma unroll
            for (int et = 0; et < 8; et++) {
                int evl = et * 8 + 2 * tig;
                stage[evl * 132 + r0 + g]           = acc[et][0];
                stage[(evl + 1) * 132 + r0 + g]     = acc[et][1];
                stage[evl * 132 + r0 + g + 8]       = acc[et][2];
                stage[(evl + 1) * 132 + r0 + g + 8] = acc[et][3];
            }
        }
        __syncthreads();
        if (!half) {
            #pragma unroll
            for (int et = 0; et < 8; et++) {
                int evl = et * 8 + 2 * tig;
                float* s0 = stage + evl * 132;
                float* s1 = stage + (evl + 1) * 132;
                s0[r0 + g]     = fmaxf(acc[et][0] + s0[r0 + g]     + b0r, 0.f);
                s1[r0 + g]     = fmaxf(acc[et][1] + s1[r0 + g]     + b0r, 0.f);
                s0[r0 + g + 8] = fmaxf(acc[et][2] + s0[r0 + g + 8] + b1r, 0.f);
                s1[r0 + g + 8] = fmaxf(acc[et][3] + s1[r0 + g + 8] + b1r, 0.f);
            }
        }
        __syncthreads();

        #pragma unroll
        for (int it = 0; it < 4; it++) {
            int idx = tid + it * 512;
            int ev = idx >> 5, q = idx & 31;
            int e = e0 + ev;
            int key = side ? dst[e] : src[e];
            float4 v = *(const float4*)(stage + ev * 132 + q * 4);
            atomicAdd((float4*)&g_sums[(size_t)key * DD + q * 4], v);
        }
        if (tid < 64) {
            int e = e0 + tid;
            int key = side ? dst[e] : src[e];
            atomicAdd(&g_cnt[key], 1.0f);
            atomicMax(&g_tmax[key], tt[e]);
        }
        __syncthreads();
        buf ^= 1;
    }
#undef GATHER
}

// ============================================================
// Fused GRU: gi = aggr@Wih^T+bih (staged fp32 in smem), gh = mem@Whh^T+bhh,
// then combine -> out. 384 thr / 12 warps, 32 nodes/tile, single fp16 sweep.
// ============================================================
__global__ void __launch_bounds__(384, 1) k_gru(
    const float* __restrict__ bih, const float* __restrict__ bhh,
    const float* __restrict__ mem, float* __restrict__ out)
{
    extern __shared__ char smem[];
    uint32_t* xgi = (uint32_t*)(smem + G2_XGI);
    uint32_t* xgh = (uint32_t*)(smem + G2_XGH);
    float* sgi = (float*)(smem + G2_SGI);
    float* sgh = (float*)(smem + G2_SGH);

    const int tid = threadIdx.x;
    const int wid = tid >> 5;
    const int lane = tid & 31;
    const int g = lane >> 2, tig = lane & 3;
    const int stride = gridDim.x * 32;

    float bvi[2][2], bvh[2][2];
    #pragma unroll
    for (int rt = 0; rt < 2; rt++) {
        int r = wid * 32 + rt * 16 + g;
        bvi[rt][0] = bih[r]; bvi[rt][1] = bih[r + 8];
        bvh[rt][0] = bhh[r]; bvh[rt][1] = bhh[r + 8];
    }

    float4 pv[3]; float pc[3]; uint4 pu[2];
#define PREF(N0) do {                                                      \
    _Pragma("unroll")                                                      \
    for (int it = 0; it < 3; it++) {                                       \
        int idx = tid + it * 384;                                          \
        if (idx < 1024) {                                                  \
            int n = (N0) + (idx >> 5);                                     \
            pv[it] = ((const float4*)g_sums)[(size_t)n * 32 + (idx & 31)]; \
            pc[it] = g_cnt[n];                                             \
        }                                                                  \
    }                                                                      \
    _Pragma("unroll")                                                      \
    for (int it = 0; it < 2; it++) {                                       \
        int idx = tid + it * 384;                                          \
        if (idx < 512) {                                                   \
            int n = (N0) + (idx >> 4), c16 = idx & 15;                     \
            pu[it] = *(const uint4*)(g_memh + (size_t)n * 64 + c16 * 4);   \
        }                                                                  \
    }                                                                      \
} while (0)

    PREF(blockIdx.x * 32);
    for (int n0 = blockIdx.x * 32; n0 < NN; n0 += stride) {
        // ---- STS both X tiles (xgi/xgh free; epilogue(t-1) done before sync) ----
        #pragma unroll
        for (int it = 0; it < 3; it++) {
            int idx = tid + it * 384;
            if (idx < 1024) {
                int n = idx >> 5, c4 = idx & 31;
                float inv = 1.0f / fmaxf(pc[it], 1.0f);
                float4 v = pv[it];
                int q = c4 & 3;
                int w = (c4 >> 2) * 8 + (q >> 1) + (q & 1) * 4;
                xgi[n * GXW + w]     = hpack(v.x * inv, v.y * inv);
                xgi[n * GXW + w + 2] = hpack(v.z * inv, v.w * inv);
            }
        }
        #pragma unroll
        for (int it = 0; it < 2; it++) {
            int idx = tid + it * 384;
            if (idx < 512) {
                int n = idx >> 4, c16 = idx & 15;
                *(uint4*)(xgh + n * GXW + c16 * 4) = pu[it];
            }
        }
        __syncthreads();
        if (n0 + stride < NN) PREF(n0 + stride);

        // ---- GEMM 1: gi ----
        {
            float acc[2][4][4];
            #pragma unroll
            for (int rt = 0; rt < 2; rt++)
                #pragma unroll
                for (int et = 0; et < 4; et++)
                    acc[rt][et][0] = acc[rt][et][1] = acc[rt][et][2] = acc[rt][et][3] = 0.f;
            #pragma unroll 1
            for (int kk = 0; kk < 8; kk++) {
                uint2 b[4];
                #pragma unroll
                for (int et = 0; et < 4; et++)
                    b[et] = *(const uint2*)(xgi + (et * 8 + g) * GXW + kk * 8 + 2 * tig);
                #pragma unroll
                for (int rt = 0; rt < 2; rt++) {
                    uint4 wh = __ldg(&g_gwh[(((size_t)(wid * 2 + rt)) * 8 + kk) * 32 + lane]);
                    #pragma unroll
                    for (int et = 0; et < 4; et++)
                        mma_h(acc[rt][et], wh.x, wh.y, wh.z, wh.w, b[et].x, b[et].y);
                }
            }
            #pragma unroll
            for (int rt = 0; rt < 2; rt++) {
                int r = wid * 32 + rt * 16 + g;
                #pragma unroll
                for (int et = 0; et < 4; et++) {
                    int nl = et * 8 + 2 * tig;
                    sgi[nl * GSTG + r]           = acc[rt][et][0] + bvi[rt][0];
                    sgi[(nl + 1) * GSTG + r]     = acc[rt][et][1] + bvi[rt][0];
                    sgi[nl * GSTG + r + 8]       = acc[rt][et][2] + bvi[rt][1];
                    sgi[(nl + 1) * GSTG + r + 8] = acc[rt][et][3] + bvi[rt][1];
                }
            }
        }
        // ---- GEMM 2: gh ----
        {
            float acc[2][4][4];
            #pragma unroll
            for (int rt = 0; rt < 2; rt++)
                #pragma unroll
                for (int et = 0; et < 4; et++)
                    acc[rt][et][0] = acc[rt][et][1] = acc[rt][et][2] = acc[rt][et][3] = 0.f;
            #pragma unroll 1
            for (int kk = 0; kk < 8; kk++) {
                uint2 b[4];
                #pragma unroll
                for (int et = 0; et < 4; et++)
                    b[et] = *(const uint2*)(xgh + (et * 8 + g) * GXW + kk * 8 + 2 * tig);
                #pragma unroll
                for (int rt = 0; rt < 2; rt++) {
                    uint4 wh = __ldg(&g_gwh[(((size_t)24 + (wid * 2 + rt)) * 8 + kk) * 32 + lane]);
                    #pragma unroll
                    for (int et = 0; et < 4; et++)
                        mma_h(acc[rt][et], wh.x, wh.y, wh.z, wh.w, b[et].x, b[et].y);
                }
            }
            #pragma unroll
            for (int rt = 0; rt < 2; rt++) {
                int r = wid * 32 + rt * 16 + g;
                #pragma unroll
                for (int et = 0; et < 4; et++) {
                    int nl = et * 8 + 2 * tig;
                    sgh[nl * GSTG + r]           = acc[rt][et][0] + bvh[rt][0];
                    sgh[(nl + 1) * GSTG + r]     = acc[rt][et][1] + bvh[rt][0];
                    sgh[nl * GSTG + r + 8]       = acc[rt][et][2] + bvh[rt][1];
                    sgh[(nl + 1) * GSTG + r + 8] = acc[rt][et][3] + bvh[rt][1];
                }
            }
        }
        __syncthreads();

        // ---- fused GRU combine (gi fp32 from smem, mem fp32 from global) ----
        #pragma unroll
        for (int it = 0; it < 3; it++) {
            int idx = tid + it * 384;
            if (idx < 1024) {
                int n = idx >> 5, c4 = idx & 31;
                float4 ir = *(const float4*)(sgi + n * GSTG + c4 * 4);
                float4 iz = *(const float4*)(sgi + n * GSTG + 128 + c4 * 4);
                float4 in_ = *(const float4*)(sgi + n * GSTG + 256 + c4 * 4);
                float4 hr = *(const float4*)(sgh + n * GSTG + c4 * 4);
                float4 hz = *(const float4*)(sgh + n * GSTG + 128 + c4 * 4);
                float4 hn = *(const float4*)(sgh + n * GSTG + 256 + c4 * 4);
                float4 m = ((const float4*)mem)[(size_t)(n0 + n) * 32 + c4];
                float4 o;
                { float rg = 1.f/(1.f+expf(-(ir.x+hr.x))), zg = 1.f/(1.f+expf(-(iz.x+hz.x)));
                  o.x = (1.f-zg)*tanhf(in_.x+rg*hn.x) + zg*m.x; }
                { float rg = 1.f/(1.f+expf(-(ir.y+hr.y))), zg = 1.f/(1.f+expf(-(iz.y+hz.y)));
                  o.y = (1.f-zg)*tanhf(in_.y+rg*hn.y) + zg*m.y; }
                { float rg = 1.f/(1.f+expf(-(ir.z+hr.z))), zg = 1.f/(1.f+expf(-(iz.z+hz.z)));
                  o.z = (1.f-zg)*tanhf(in_.z+rg*hn.z) + zg*m.z; }
                { float rg = 1.f/(1.f+expf(-(ir.w+hr.w))), zg = 1.f/(1.f+expf(-(iz.w+hz.w)));
                  o.w = (1.f-zg)*tanhf(in_.w+rg*hn.w) + zg*m.w; }
                ((float4*)out)[(size_t)(n0 + n) * 32 + c4] = o;
            }
        }
        // next iteration's leading sync orders epilogue reads before stage writes
    }
#undef PREF
}

// ============================================================
__global__ void k_lu(float* __restrict__ out) {
    int i = blockIdx.x * blockDim.x + threadIdx.x;
    if (i < NN)
        out[(size_t)NN * DD + i] = (g_cnt[i] > 0.f) ? (float)g_tmax[i] : 0.f;
}

// ============================================================
extern "C" void kernel_launch(void* const* d_in, const int* in_sizes, int n_in,
                              void* d_out, int out_size)
{
    const float* mem = (const float*)d_in[0];
    const float* raw = (const float*)d_in[1];
    const float* tw  = (const float*)d_in[2];
    const float* tb  = (const float*)d_in[3];
    const float* Ws  = (const float*)d_in[4];
    const float* bs  = (const float*)d_in[5];
    const float* Wd  = (const float*)d_in[6];
    const float* bd  = (const float*)d_in[7];
    const float* Wih = (const float*)d_in[8];
    const float* Whh = (const float*)d_in[9];
    const float* bih = (const float*)d_in[10];
    const float* bhh = (const float*)d_in[11];
    const int* src = (const int*)d_in[12];
    const int* dst = (const int*)d_in[13];
    const int* tt  = (const int*)d_in[14];
    const int* lu  = (const int*)d_in[15];
    float* out = (float*)d_out;

    cudaFuncSetAttribute(k_msgT, cudaFuncAttributeMaxDynamicSharedMemorySize, SMEM_MSG);
    cudaFuncSetAttribute(k_gru,  cudaFuncAttributeMaxDynamicSharedMemorySize, SMEM_GRU2);

    k_init<<<2048, 256>>>();
    k_pack<<<416, 32>>>(Ws, Wd);
    k_packgru<<<384, 32>>>(Wih, Whh);
    k_packmem<<<2048, 256>>>(mem);
    k_packraw<<<2048, 256>>>(raw);
    k_msgT<<<2 * NB, 512, SMEM_MSG>>>(tw, tb, bs, bd, src, dst, tt, lu);
    k_gru<<<NB, 384, SMEM_GRU2>>>(bih, bhh, mem, out);
    if (out_size >= NN * DD + NN)
        k_lu<<<(NN + 255) / 256, 256>>>(out);
}

// round 17
// speedup vs baseline: 1.2495x; 1.0281x over previous
#include <cuda_runtime.h>
#include <cuda_fp16.h>
#include <math.h>
#include <stdint.h>

#define NN 131072
#define EE 262144
#define DD 128
#define RR 128
#define NB 148
#define GOUT 384

#define TWO_PI_C1 6.2831854820251465f
#define TWO_PI_C2 (-1.7484556e-7f)
#define INV_2PI   0.15915494309189535f

// ---- k_msgT smem: double-buffered fp16 X ----
#define MXW 212
#define MXROW (MXW * 4)
#define XBUF 54272
#define SMEM_MSG (2 * XBUF)             // 108544 -> 2 CTAs/SM

// ---- fused GRU smem (16-node tiles) ----
#define GXW 72
#define GSTG 388
#define G2_XGI 0                        // 16*72*4 = 4608
#define G2_XGH 4608                     // 4608
#define G2_SGI 9216                     // 16*388*4 = 24832
#define G2_SGH (9216 + 24832)           // 34048
#define SMEM_GRU2 (34048 + 24832)       // 58880 -> 2 CTAs/SM

// -------- device scratch --------
__device__ float g_sums[(size_t)NN * DD];
__device__ float g_cnt[NN];
__device__ int   g_tmax[NN];
__device__ uint4 g_wph[2 * 8 * 26 * 32];          // msg W fp16 fragments
__device__ uint4 g_gwh[2 * 24 * 8 * 32];          // GRU W fp16 fragments
__device__ uint32_t g_memh[(size_t)NN * 64];      // memory fp16, permuted
__device__ uint32_t g_rawh[(size_t)EE * 64];      // raw fp16, permuted

// ================= helpers =================
__device__ __forceinline__ void mma_h(float* c,
                                      uint32_t a0, uint32_t a1, uint32_t a2, uint32_t a3,
                                      uint32_t b0, uint32_t b1) {
    asm volatile("mma.sync.aligned.m16n8k16.row.col.f32.f16.f16.f32 "
        "{%0,%1,%2,%3}, {%4,%5,%6,%7}, {%8,%9}, {%0,%1,%2,%3};"
        : "+f"(c[0]), "+f"(c[1]), "+f"(c[2]), "+f"(c[3])
        : "r"(a0), "r"(a1), "r"(a2), "r"(a3), "r"(b0), "r"(b1));
}
__device__ __forceinline__ uint32_t hpack(float x, float y) {
    __half2 h = __floats2half2_rn(x, y);
    return *reinterpret_cast<uint32_t*>(&h);
}
__device__ __forceinline__ float cos_exact(float arg) {
    float k = rintf(__fmul_rn(arg, INV_2PI));
    float r = fmaf(-k, TWO_PI_C1, arg);
    r = fmaf(-k, TWO_PI_C2, r);
    return cosf(r);
}
__device__ __forceinline__ int permslot(int p) {
    int kk = p >> 3, pi = p & 7;
    return kk * 8 + ((pi < 4) ? 2 * pi : 2 * (pi - 4) + 1);
}
__device__ __forceinline__ uint32_t smem_u32(const void* p) {
    uint32_t a;
    asm("{ .reg .u64 t; cvta.to.shared.u64 t, %1; cvt.u32.u64 %0, t; }" : "=r"(a) : "l"(p));
    return a;
}
__device__ __forceinline__ void cp16(uint32_t dst, const void* src) {
    asm volatile("cp.async.cg.shared.global [%0], [%1], 16;" :: "r"(dst), "l"(src) : "memory");
}
#define CP_COMMIT() asm volatile("cp.async.commit_group;" ::: "memory")
#define CP_WAIT0()  asm volatile("cp.async.wait_group 0;" ::: "memory")

// ============================================================
__global__ void k_init() {
    size_t i = (size_t)blockIdx.x * blockDim.x + threadIdx.x;
    size_t stride = (size_t)gridDim.x * blockDim.x;
    float4* s4 = (float4*)g_sums;
    for (size_t idx = i; idx < (size_t)NN * DD / 4; idx += stride)
        s4[idx] = make_float4(0.f, 0.f, 0.f, 0.f);
    for (size_t idx = i; idx < NN; idx += stride) { g_cnt[idx] = 0.f; g_tmax[idx] = 0; }
}

// ============================================================
__global__ void k_packmem(const float* __restrict__ mem) {
    size_t i = (size_t)blockIdx.x * blockDim.x + threadIdx.x;
    size_t stride = (size_t)gridDim.x * blockDim.x;
    for (size_t idx = i; idx < (size_t)NN * 64; idx += stride) {
        size_t n = idx >> 6; int p = (int)(idx & 63);
        float2 v = *(const float2*)(mem + n * 128 + 2 * p);
        g_memh[n * 64 + permslot(p)] = hpack(v.x, v.y);
    }
}
__global__ void k_packraw(const float* __restrict__ raw) {
    size_t i = (size_t)blockIdx.x * blockDim.x + threadIdx.x;
    size_t stride = (size_t)gridDim.x * blockDim.x;
    for (size_t idx = i; idx < (size_t)EE * 64; idx += stride) {
        size_t e = idx >> 6; int p = (int)(idx & 63);
        float2 v = *(const float2*)(raw + e * 128 + 2 * p);
        g_rawh[e * 64 + permslot(p)] = hpack(v.x, v.y);
    }
}

// ============================================================
__global__ void k_pack(const float* __restrict__ Ws, const float* __restrict__ Wd) {
    int lane = threadIdx.x;
    int b = blockIdx.x;
    int side = b / 208;
    int rem = b - side * 208;
    int rg = rem / 26, kg = rem - (rem / 26) * 26;
    const float* W = side ? Wd : Ws;
    int g = lane >> 2, tig = lane & 3;
    int r0 = rg * 16;
    int rows[2] = {r0 + g, r0 + g + 8};
    int cols[2] = {kg * 16 + 2 * tig, kg * 16 + 8 + 2 * tig};
    uint32_t wh[4];
    #pragma unroll
    for (int cc = 0; cc < 2; cc++)
        #pragma unroll
        for (int rr = 0; rr < 2; rr++) {
            float2 v = *(const float2*)(W + (size_t)rows[rr] * 416 + cols[cc]);
            wh[cc * 2 + rr] = hpack(v.x, v.y);
        }
    g_wph[(size_t)b * 32 + lane] = make_uint4(wh[0], wh[1], wh[2], wh[3]);
}

__global__ void k_packgru(const float* __restrict__ Wih, const float* __restrict__ Whh) {
    int lane = threadIdx.x;
    int b = blockIdx.x;
    int m = b / 192;
    int rem = b - m * 192;
    int rtile = rem >> 3, kk = rem & 7;
    const float* W = m ? Whh : Wih;
    int g = lane >> 2, tig = lane & 3;
    int r0 = rtile * 16;
    int rows[2] = {r0 + g, r0 + g + 8};
    int cols[2] = {kk * 16 + 2 * tig, kk * 16 + 8 + 2 * tig};
    uint32_t wh[4];
    #pragma unroll
    for (int cc = 0; cc < 2; cc++)
        #pragma unroll
        for (int rr = 0; rr < 2; rr++) {
            float2 v = *(const float2*)(W + (size_t)rows[rr] * 128 + cols[cc]);
            wh[cc * 2 + rr] = hpack(v.x, v.y);
        }
    g_gwh[(size_t)b * 32 + lane] = make_uint4(wh[0], wh[1], wh[2], wh[3]);
}

// ============================================================
// Message MLP: fp16 single-sweep, full-K warps (no K-split),
// cp.async double-buffered gather. 512 thr / 16 warps:
//   rw = wid&7 -> rows rw*16..+16 ; eg = wid>>3 -> events eg*32..+32.
// ============================================================
__global__ void __launch_bounds__(512, 2) k_msgT(
    const float* __restrict__ tw,  const float* __restrict__ tb,
    const float* __restrict__ bs,  const float* __restrict__ bd,
    const int* __restrict__ src, const int* __restrict__ dst,
    const int* __restrict__ tt,  const int* __restrict__ lu)
{
    extern __shared__ char smem[];
    const uint32_t sb = smem_u32(smem);

    const int tid  = threadIdx.x;
    const int wid  = tid >> 5;
    const int lane = tid & 31;
    const int g    = lane >> 2;
    const int tig  = lane & 3;
    const int rw   = wid & 7;
    const int eg   = wid >> 3;
    const int side = (blockIdx.x >= NB);
    const int bid  = side ? blockIdx.x - NB : blockIdx.x;
    const float* bias = side ? bd : bs;
    const int r0 = rw * 16;
    const size_t wbase = ((size_t)side * 208 + (size_t)rw * 26) * 32 + lane;

    const float b0r = bias[r0 + g], b1r = bias[r0 + g + 8];
    const float twj = tw[lane], tbj = tb[lane];
    const int STRIDE = NB * 64;

    // hygiene: no inner variable may shadow the caller's buffer index.
#define GATHER(E0, BO) do {                                                   \
    uint32_t xdst = sb + (uint32_t)(BO);                                      \
    _Pragma("unroll")                                                         \
    for (int it = 0; it < 6; it++) {                                          \
        int idx = tid + it * 512;                                             \
        int ev = idx / 48, c16 = idx - (idx / 48) * 48;                       \
        int e = (E0) + ev;                                                    \
        int vs = src[e], vd = dst[e];                                         \
        int a = side ? vd : vs, b = side ? vs : vd;                           \
        size_t base; const uint32_t* ph;                                      \
        if (c16 < 16)      { base = (size_t)a * 64 + c16 * 4;        ph = g_memh; } \
        else if (c16 < 32) { base = (size_t)b * 64 + (c16 - 16) * 4; ph = g_memh; } \
        else               { base = (size_t)e * 64 + (c16 - 32) * 4; ph = g_rawh; } \
        cp16(xdst + (uint32_t)(ev * MXROW + c16 * 16), ph + base);            \
    }                                                                         \
    CP_COMMIT();                                                              \
    _Pragma("unroll")                                                         \
    for (int z = 0; z < 4; z++) {                                             \
        int ev = wid + z * 16;                                                \
        int e = (E0) + ev;                                                    \
        int a = side ? dst[e] : src[e];                                       \
        float trel = __fsub_rn((float)tt[e], (float)lu[a]);                   \
        float arg  = __fadd_rn(__fmul_rn(trel, twj), tbj);                    \
        float c = cos_exact(arg);                                             \
        int kwd  = 384 + lane;                                                \
        int pw   = kwd >> 1;                                                  \
        int pi = pw & 7, kq = pw >> 3;                                        \
        int w = kq * 8 + ((pi < 4) ? 2 * pi : 2 * (pi - 4) + 1);              \
        *(__half*)((char*)smem + (uint32_t)(BO) + ev * MXROW + w * 4 + (kwd & 1) * 2) = \
            __float2half_rn(c);                                               \
    }                                                                         \
} while (0)

    GATHER(bid * 64, 0);
    int buf = 0;

    for (int e0 = bid * 64; e0 < EE; e0 += STRIDE) {
        CP_WAIT0();
        __syncthreads();
        int e1 = e0 + STRIDE;
        if (e1 < EE) GATHER(e1, (buf ^ 1) * XBUF);

        uint32_t* xh = (uint32_t*)(smem + buf * XBUF);
        float* stage = (float*)(smem + buf * XBUF);

        // ---- mma: single fp16 sweep, full K = 26 ksteps, 4 event-tiles ----
        float acc[4][4];
        #pragma unroll
        for (int et = 0; et < 4; et++)
            acc[et][0] = acc[et][1] = acc[et][2] = acc[et][3] = 0.f;
        #pragma unroll 1
        for (int kk = 0; kk < 26; kk++) {
            uint4 wh = __ldg(&g_wph[wbase + (size_t)kk * 32]);
            #pragma unroll
            for (int et = 0; et < 4; et++) {
                uint2 b = *(const uint2*)(xh + (eg * 32 + et * 8 + g) * MXW + kk * 8 + 2 * tig);
                mma_h(acc[et], wh.x, wh.y, wh.z, wh.w, b.x, b.y);
            }
        }
        __syncthreads();            // xh reads done -> stage overlays

        // ---- relu + bias, direct to stage (no K-combine needed) ----
        #pragma unroll
        for (int et = 0; et < 4; et++) {
            int evl = eg * 32 + et * 8 + 2 * tig;
            float* s0 = stage + evl * 132;
            float* s1 = stage + (evl + 1) * 132;
            s0[r0 + g]     = fmaxf(acc[et][0] + b0r, 0.f);
            s1[r0 + g]     = fmaxf(acc[et][1] + b0r, 0.f);
            s0[r0 + g + 8] = fmaxf(acc[et][2] + b1r, 0.f);
            s1[r0 + g + 8] = fmaxf(acc[et][3] + b1r, 0.f);
        }
        __syncthreads();

        // ---- scatter float4 atomics ----
        #pragma unroll
        for (int it = 0; it < 4; it++) {
            int idx = tid + it * 512;
            int ev = idx >> 5, q = idx & 31;
            int e = e0 + ev;
            int key = side ? dst[e] : src[e];
            float4 v = *(const float4*)(stage + ev * 132 + q * 4);
            atomicAdd((float4*)&g_sums[(size_t)key * DD + q * 4], v);
        }
        if (tid < 64) {
            int e = e0 + tid;
            int key = side ? dst[e] : src[e];
            atomicAdd(&g_cnt[key], 1.0f);
            atomicMax(&g_tmax[key], tt[e]);
        }
        __syncthreads();
        buf ^= 1;
    }
#undef GATHER
}

// ============================================================
// Fused GRU + last_update. 16-node tiles, 384 thr, 2 CTAs/SM, grid 2*NB.
// ============================================================
__global__ void __launch_bounds__(384, 2) k_gru(
    const float* __restrict__ bih, const float* __restrict__ bhh,
    const float* __restrict__ mem, float* __restrict__ out, int haslu)
{
    extern __shared__ char smem[];
    uint32_t* xgi = (uint32_t*)(smem + G2_XGI);
    uint32_t* xgh = (uint32_t*)(smem + G2_XGH);
    float* sgi = (float*)(smem + G2_SGI);
    float* sgh = (float*)(smem + G2_SGH);

    const int tid = threadIdx.x;
    const int wid = tid >> 5;
    const int lane = tid & 31;
    const int g = lane >> 2, tig = lane & 3;
    const int stride = gridDim.x * 16;

    float bvi[2][2], bvh[2][2];
    #pragma unroll
    for (int rt = 0; rt < 2; rt++) {
        int r = wid * 32 + rt * 16 + g;
        bvi[rt][0] = bih[r]; bvi[rt][1] = bih[r + 8];
        bvh[rt][0] = bhh[r]; bvh[rt][1] = bhh[r + 8];
    }

    float4 pv[2]; float pc[2]; uint4 pu;
#define PREF(N0) do {                                                      \
    _Pragma("unroll")                                                      \
    for (int it = 0; it < 2; it++) {                                       \
        int idx = tid + it * 384;                                          \
        if (idx < 512) {                                                   \
            int n = (N0) + (idx >> 5);                                     \
            pv[it] = ((const float4*)g_sums)[(size_t)n * 32 + (idx & 31)]; \
            pc[it] = g_cnt[n];                                             \
        }                                                                  \
    }                                                                      \
    if (tid < 256) {                                                       \
        int n = (N0) + (tid >> 4), c16 = tid & 15;                         \
        pu = *(const uint4*)(g_memh + (size_t)n * 64 + c16 * 4);           \
    }                                                                      \
} while (0)

    PREF(blockIdx.x * 16);
    for (int n0 = blockIdx.x * 16; n0 < NN; n0 += stride) {
        // ---- STS both X tiles ----
        #pragma unroll
        for (int it = 0; it < 2; it++) {
            int idx = tid + it * 384;
            if (idx < 512) {
                int n = idx >> 5, c4 = idx & 31;
                float inv = 1.0f / fmaxf(pc[it], 1.0f);
                float4 v = pv[it];
                int q = c4 & 3;
                int w = (c4 >> 2) * 8 + (q >> 1) + (q & 1) * 4;
                xgi[n * GXW + w]     = hpack(v.x * inv, v.y * inv);
                xgi[n * GXW + w + 2] = hpack(v.z * inv, v.w * inv);
            }
        }
        if (tid < 256) {
            int n = tid >> 4, c16 = tid & 15;
            *(uint4*)(xgh + n * GXW + c16 * 4) = pu;
        }
        __syncthreads();    // also fences prev tile's combine reads vs these writes
        if (n0 + stride < NN) PREF(n0 + stride);

        // ---- GEMM 1: gi ----
        {
            float acc[2][2][4];
            #pragma unroll
            for (int rt = 0; rt < 2; rt++)
                #pragma unroll
                for (int et = 0; et < 2; et++)
                    acc[rt][et][0] = acc[rt][et][1] = acc[rt][et][2] = acc[rt][et][3] = 0.f;
            #pragma unroll 1
            for (int kk = 0; kk < 8; kk++) {
                uint2 b[2];
                #pragma unroll
                for (int et = 0; et < 2; et++)
                    b[et] = *(const uint2*)(xgi + (et * 8 + g) * GXW + kk * 8 + 2 * tig);
                #pragma unroll
                for (int rt = 0; rt < 2; rt++) {
                    uint4 wh = __ldg(&g_gwh[(((size_t)(wid * 2 + rt)) * 8 + kk) * 32 + lane]);
                    #pragma unroll
                    for (int et = 0; et < 2; et++)
                        mma_h(acc[rt][et], wh.x, wh.y, wh.z, wh.w, b[et].x, b[et].y);
                }
            }
            #pragma unroll
            for (int rt = 0; rt < 2; rt++) {
                int r = wid * 32 + rt * 16 + g;
                #pragma unroll
                for (int et = 0; et < 2; et++) {
                    int nl = et * 8 + 2 * tig;
                    sgi[nl * GSTG + r]           = acc[rt][et][0] + bvi[rt][0];
                    sgi[(nl + 1) * GSTG + r]     = acc[rt][et][1] + bvi[rt][0];
                    sgi[nl * GSTG + r + 8]       = acc[rt][et][2] + bvi[rt][1];
                    sgi[(nl + 1) * GSTG + r + 8] = acc[rt][et][3] + bvi[rt][1];
                }
            }
        }
        // ---- GEMM 2: gh ----
        {
            float acc[2][2][4];
            #pragma unroll
            for (int rt = 0; rt < 2; rt++)
                #pragma unroll
                for (int et = 0; et < 2; et++)
                    acc[rt][et][0] = acc[rt][et][1] = acc[rt][et][2] = acc[rt][et][3] = 0.f;
            #pragma unroll 1
            for (int kk = 0; kk < 8; kk++) {
                uint2 b[2];
                #pragma unroll
                for (int et = 0; et < 2; et++)
                    b[et] = *(const uint2*)(xgh + (et * 8 + g) * GXW + kk * 8 + 2 * tig);
                #pragma unroll
                for (int rt = 0; rt < 2; rt++) {
                    uint4 wh = __ldg(&g_gwh[(((size_t)24 + (wid * 2 + rt)) * 8 + kk) * 32 + lane]);
                    #pragma unroll
                    for (int et = 0; et < 2; et++)
                        mma_h(acc[rt][et], wh.x, wh.y, wh.z, wh.w, b[et].x, b[et].y);
                }
            }
            #pragma unroll
            for (int rt = 0; rt < 2; rt++) {
                int r = wid * 32 + rt * 16 + g;
                #pragma unroll
                for (int et = 0; et < 2; et++) {
                    int nl = et * 8 + 2 * tig;
                    sgh[nl * GSTG + r]           = acc[rt][et][0] + bvh[rt][0];
                    sgh[(nl + 1) * GSTG + r]     = acc[rt][et][1] + bvh[rt][0];
                    sgh[nl * GSTG + r + 8]       = acc[rt][et][2] + bvh[rt][1];
                    sgh[(nl + 1) * GSTG + r + 8] = acc[rt][et][3] + bvh[rt][1];
                }
            }
        }
        __syncthreads();

        // ---- fused GRU combine ----
        #pragma unroll
        for (int it = 0; it < 2; it++) {
            int idx = tid + it * 384;
            if (idx < 512) {
                int n = idx >> 5, c4 = idx & 31;
                float4 ir = *(const float4*)(sgi + n * GSTG + c4 * 4);
                float4 iz = *(const float4*)(sgi + n * GSTG + 128 + c4 * 4);
                float4 in_ = *(const float4*)(sgi + n * GSTG + 256 + c4 * 4);
                float4 hr = *(const float4*)(sgh + n * GSTG + c4 * 4);
                float4 hz = *(const float4*)(sgh + n * GSTG + 128 + c4 * 4);
                float4 hn = *(const float4*)(sgh + n * GSTG + 256 + c4 * 4);
                float4 m = ((const float4*)mem)[(size_t)(n0 + n) * 32 + c4];
                float4 o;
                { float rg = 1.f/(1.f+expf(-(ir.x+hr.x))), zg = 1.f/(1.f+expf(-(iz.x+hz.x)));
                  o.x = (1.f-zg)*tanhf(in_.x+rg*hn.x) + zg*m.x; }
                { float rg = 1.f/(1.f+expf(-(ir.y+hr.y))), zg = 1.f/(1.f+expf(-(iz.y+hz.y)));
                  o.y = (1.f-zg)*tanhf(in_.y+rg*hn.y) + zg*m.y; }
                { float rg = 1.f/(1.f+expf(-(ir.z+hr.z))), zg = 1.f/(1.f+expf(-(iz.z+hz.z)));
                  o.z = (1.f-zg)*tanhf(in_.z+rg*hn.z) + zg*m.z; }
                { float rg = 1.f/(1.f+expf(-(ir.w+hr.w))), zg = 1.f/(1.f+expf(-(iz.w+hz.w)));
                  o.w = (1.f-zg)*tanhf(in_.w+rg*hn.w) + zg*m.w; }
                ((float4*)out)[(size_t)(n0 + n) * 32 + c4] = o;
            }
        }
        // ---- fused last_update ----
        if (haslu && tid < 16) {
            int n = n0 + tid;
            out[(size_t)NN * DD + n] = (g_cnt[n] > 0.f) ? (float)g_tmax[n] : 0.f;
        }
        // next iteration's leading sync orders combine reads before stage writes
    }
#undef PREF
}

// ============================================================
extern "C" void kernel_launch(void* const* d_in, const int* in_sizes, int n_in,
                              void* d_out, int out_size)
{
    const float* mem = (const float*)d_in[0];
    const float* raw = (const float*)d_in[1];
    const float* tw  = (const float*)d_in[2];
    const float* tb  = (const float*)d_in[3];
    const float* Ws  = (const float*)d_in[4];
    const float* bs  = (const float*)d_in[5];
    const float* Wd  = (const float*)d_in[6];
    const float* bd  = (const float*)d_in[7];
    const float* Wih = (const float*)d_in[8];
    const float* Whh = (const float*)d_in[9];
    const float* bih = (const float*)d_in[10];
    const float* bhh = (const float*)d_in[11];
    const int* src = (const int*)d_in[12];
    const int* dst = (const int*)d_in[13];
    const int* tt  = (const int*)d_in[14];
    const int* lu  = (const int*)d_in[15];
    float* out = (float*)d_out;

    cudaFuncSetAttribute(k_msgT, cudaFuncAttributeMaxDynamicSharedMemorySize, SMEM_MSG);
    cudaFuncSetAttribute(k_gru,  cudaFuncAttributeMaxDynamicSharedMemorySize, SMEM_GRU2);

    int haslu = (out_size >= NN * DD + NN) ? 1 : 0;

    k_init<<<2048, 256>>>();
    k_pack<<<416, 32>>>(Ws, Wd);
    k_packgru<<<384, 32>>>(Wih, Whh);
    k_packmem<<<2048, 256>>>(mem);
    k_packraw<<<2048, 256>>>(raw);
    k_msgT<<<2 * NB, 512, SMEM_MSG>>>(tw, tb, bs, bd, src, dst, tt, lu);
    k_gru<<<2 * NB, 384, SMEM_GRU2>>>(bih, bhh, mem, out, haslu);
}